// round 4
// baseline (speedup 1.0000x reference)
#include <cuda_runtime.h>

typedef unsigned long long u64;

// Packed f32x2 carrier. Lane0 = row A, lane1 = row B. All packed ops are
// per-lane IEEE .rn — bit-identical to the scalar __f*_rn versions.
struct P { u64 v; };

__device__ __forceinline__ P mk2(float a, float b) {
    P r; asm("mov.b64 %0, {%1, %2};" : "=l"(r.v) : "f"(a), "f"(b)); return r;
}
__device__ __forceinline__ void un2(P a, float& x, float& y) {
    asm("mov.b64 {%0, %1}, %2;" : "=f"(x), "=f"(y) : "l"(a.v));
}
__device__ __forceinline__ P pmul(P a, P b) {
    P r; asm("mul.rn.f32x2 %0, %1, %2;" : "=l"(r.v) : "l"(a.v), "l"(b.v)); return r;
}
__device__ __forceinline__ P padd(P a, P b) {
    P r; asm("add.rn.f32x2 %0, %1, %2;" : "=l"(r.v) : "l"(a.v), "l"(b.v)); return r;
}
__device__ __forceinline__ P pfma(P a, P b, P c) {
    P r; asm("fma.rn.f32x2 %0, %1, %2, %3;" : "=l"(r.v) : "l"(a.v), "l"(b.v), "l"(c.v)); return r;
}
// rn(a - b): b*(-1) is exact, single rounding => bit-identical to __fsub_rn per lane.
__device__ __forceinline__ P psub(P a, P b, P neg1) { return pfma(b, neg1, a); }

// Packed 2-row dynamics, replicating the reference op graph per lane.
// s = [vx,vy,vz, roll,pitch,yaw, wx,wy,wz] (each P = {rowA, rowB})
__device__ __forceinline__ void dyn9p(
    const P* __restrict__ s,
    P U0, P TXp, P TYp, P TZp,
    float I0, float I1, float I2,
    P I0P, P I1P, P I2P,
    P G0, P G1, P G2,
    P NEG1, P NEGK,
    P* __restrict__ d)
{
    float r0, r1, p0, p1, w0, w1;
    un2(s[3], r0, r1); un2(s[4], p0, p1); un2(s[5], w0, w1);

    float sr0, cr0, sr1, cr1, sp0, cp0, sp1, cp1, sy0, cy0, sy1, cy1;
    sincosf(r0, &sr0, &cr0); sincosf(r1, &sr1, &cr1);
    sincosf(p0, &sp0, &cp0); sincosf(p1, &sp1, &cp1);
    sincosf(w0, &sy0, &cy0); sincosf(w1, &sy1, &cy1);

    P SR = mk2(sr0, sr1), CR = mk2(cr0, cr1);
    P SP = mk2(sp0, sp1), CP = mk2(cp0, cp1);
    P SY = mk2(sy0, sy1), CY = mk2(cy0, cy1);

    // R[:, :, 2] thrust column: ((cy*sp)*cr) + sy*sr ; ((sy*sp)*cr) - cy*sr ; cp*cr
    P R2X = padd(pmul(pmul(CY, SP), CR), pmul(SY, SR));
    P R2Y = psub(pmul(pmul(SY, SP), CR), pmul(CY, SR), NEG1);
    P R2Z = pmul(CP, CR);

    // v_norm = max(sqrt(vx^2+vy^2+vz^2), 1e-8)
    P VX = s[0], VY = s[1], VZ = s[2];
    P N2 = padd(padd(pmul(VX, VX), pmul(VY, VY)), pmul(VZ, VZ));
    float n20, n21; un2(N2, n20, n21);
    float vn0 = fmaxf(__fsqrt_rn(n20), 1e-8f);
    float vn1 = fmaxf(__fsqrt_rn(n21), 1e-8f);
    P NK = pmul(NEGK, mk2(vn0, vn1));   // -0.05 * v_norm

    d[0] = padd(padd(pmul(R2X, U0), pmul(NK, VX)), G0);
    d[1] = padd(padd(pmul(R2Y, U0), pmul(NK, VY)), G1);
    d[2] = padd(padd(pmul(R2Z, U0), pmul(NK, VZ)), G2);

    // omega_dot = (tau - cross(omega, omega*I)) / I
    P WX = s[6], WY = s[7], WZ = s[8];
    P BX = pmul(WX, I0P), BY = pmul(WY, I1P), BZ = pmul(WZ, I2P);
    P CXV = psub(pmul(WY, BZ), pmul(WZ, BY), NEG1);
    P CYV = psub(pmul(WZ, BX), pmul(WX, BZ), NEG1);
    P CZV = psub(pmul(WX, BY), pmul(WY, BX), NEG1);
    P NXv = psub(TXp, CXV, NEG1);
    P NYv = psub(TYp, CYV, NEG1);
    P NZv = psub(TZp, CZV, NEG1);
    { float x0, x1; un2(NXv, x0, x1); d[6] = mk2(__fdiv_rn(x0, I0), __fdiv_rn(x1, I0)); }
    { float x0, x1; un2(NYv, x0, x1); d[7] = mk2(__fdiv_rn(x0, I1), __fdiv_rn(x1, I1)); }
    { float x0, x1; un2(NZv, x0, x1); d[8] = mk2(__fdiv_rn(x0, I2), __fdiv_rn(x1, I2)); }

    // attitude kinematics (separate divisions, exact reference associativity)
    float cpit0 = (fabsf(cp0) < 1e-6f) ? 1e-6f : cp0;
    float cpit1 = (fabsf(cp1) < 1e-6f) ? 1e-6f : cp1;
    P TP  = mk2(__fdiv_rn(sp0, cpit0), __fdiv_rn(sp1, cpit1));
    P SRD = mk2(__fdiv_rn(sr0, cpit0), __fdiv_rn(sr1, cpit1));
    P CRD = mk2(__fdiv_rn(cr0, cpit0), __fdiv_rn(cr1, cpit1));
    // d3 = (wx + (sr*tp)*wy) + (cr*tp)*wz
    d[3] = padd(padd(WX, pmul(pmul(SR, TP), WY)), pmul(pmul(CR, TP), WZ));
    d[4] = psub(pmul(CR, WY), pmul(SR, WZ), NEG1);
    d[5] = padd(pmul(SRD, WY), pmul(CRD, WZ));
}

__global__ void __launch_bounds__(128, 4)
drone_rk4_kernel(const float4* __restrict__ st4,
                 const float4* __restrict__ u4,
                 const float*  __restrict__ Ip,
                 const float*  __restrict__ gp,
                 float4* __restrict__ out4,
                 int B)
{
    int tid = blockIdx.x * blockDim.x + threadIdx.x;
    int i0 = 2 * tid;
    if (i0 >= B) return;
    bool has2 = (i0 + 1 < B);
    int i1 = has2 ? (i0 + 1) : i0;   // duplicate last row if odd B; store suppressed

    float4 a0 = st4[3 * i0 + 0], b0 = st4[3 * i0 + 1], c0 = st4[3 * i0 + 2];
    float4 a1 = st4[3 * i1 + 0], b1 = st4[3 * i1 + 1], c1 = st4[3 * i1 + 2];
    float4 u0v = u4[i0], u1v = u4[i1];

    float I0 = __ldg(Ip + 0), I1 = __ldg(Ip + 1), I2 = __ldg(Ip + 2);
    float g0 = __ldg(gp + 0), g1 = __ldg(gp + 1), g2 = __ldg(gp + 2);

    P U0  = mk2(u0v.x, u1v.x);
    P TXp = mk2(u0v.y, u1v.y);
    P TYp = mk2(u0v.z, u1v.z);
    P TZp = mk2(u0v.w, u1v.w);
    P I0P = mk2(I0, I0), I1P = mk2(I1, I1), I2P = mk2(I2, I2);
    P G0  = mk2(g0, g0), G1  = mk2(g1, g1), G2  = mk2(g2, g2);
    P NEG1 = mk2(-1.0f, -1.0f);
    P NEGK = mk2(-0.05f, -0.05f);
    P TWO  = mk2(2.0f, 2.0f);
    P H2P  = mk2(0.005f, 0.005f);
    P H1P  = mk2(0.01f, 0.01f);
    const float W6s = (float)(0.01 / 6.0);
    P W6P  = mk2(W6s, W6s);

    P Y[9] = { mk2(a0.w, a1.w), mk2(b0.x, b1.x), mk2(b0.y, b1.y),
               mk2(b0.z, b1.z), mk2(b0.w, b1.w), mk2(c0.x, c1.x),
               mk2(c0.y, c1.y), mk2(c0.z, c1.z), mk2(c0.w, c1.w) };

    P K[9], T[9], A[9];
    P APX, APY, APZ;

    // ---- k1 ----
    dyn9p(Y, U0, TXp, TYp, TZp, I0, I1, I2, I0P, I1P, I2P, G0, G1, G2, NEG1, NEGK, K);
    #pragma unroll
    for (int j = 0; j < 9; j++) { A[j] = K[j]; T[j] = padd(Y[j], pmul(H2P, K[j])); }
    APX = padd(Y[0], pmul(TWO, T[0]));
    APY = padd(Y[1], pmul(TWO, T[1]));
    APZ = padd(Y[2], pmul(TWO, T[2]));

    // ---- k2 ----
    dyn9p(T, U0, TXp, TYp, TZp, I0, I1, I2, I0P, I1P, I2P, G0, G1, G2, NEG1, NEGK, K);
    #pragma unroll
    for (int j = 0; j < 9; j++) { A[j] = padd(A[j], pmul(TWO, K[j])); T[j] = padd(Y[j], pmul(H2P, K[j])); }
    APX = padd(APX, pmul(TWO, T[0]));
    APY = padd(APY, pmul(TWO, T[1]));
    APZ = padd(APZ, pmul(TWO, T[2]));

    // ---- k3 ----
    dyn9p(T, U0, TXp, TYp, TZp, I0, I1, I2, I0P, I1P, I2P, G0, G1, G2, NEG1, NEGK, K);
    #pragma unroll
    for (int j = 0; j < 9; j++) { A[j] = padd(A[j], pmul(TWO, K[j])); T[j] = padd(Y[j], pmul(H1P, K[j])); }
    APX = padd(APX, T[0]);
    APY = padd(APY, T[1]);
    APZ = padd(APZ, T[2]);

    // ---- k4 ----
    dyn9p(T, U0, TXp, TYp, TZp, I0, I1, I2, I0P, I1P, I2P, G0, G1, G2, NEG1, NEGK, K);
    #pragma unroll
    for (int j = 0; j < 9; j++) A[j] = padd(A[j], K[j]);

    // out = state + (DT/6) * acc
    P OPX = padd(mk2(a0.x, a1.x), pmul(W6P, APX));
    P OPY = padd(mk2(a0.y, a1.y), pmul(W6P, APY));
    P OPZ = padd(mk2(a0.z, a1.z), pmul(W6P, APZ));
    P O[9];
    #pragma unroll
    for (int j = 0; j < 9; j++) O[j] = padd(Y[j], pmul(W6P, A[j]));

    float px0, px1, py0, py1, pz0, pz1;
    un2(OPX, px0, px1); un2(OPY, py0, py1); un2(OPZ, pz0, pz1);
    float o0[9], o1[9];
    #pragma unroll
    for (int j = 0; j < 9; j++) un2(O[j], o0[j], o1[j]);

    float4 oa0 = { px0, py0, pz0, o0[0] };
    float4 ob0 = { o0[1], o0[2], o0[3], o0[4] };
    float4 oc0 = { o0[5], o0[6], o0[7], o0[8] };
    out4[3 * i0 + 0] = oa0;
    out4[3 * i0 + 1] = ob0;
    out4[3 * i0 + 2] = oc0;

    if (has2) {
        float4 oa1 = { px1, py1, pz1, o1[0] };
        float4 ob1 = { o1[1], o1[2], o1[3], o1[4] };
        float4 oc1 = { o1[5], o1[6], o1[7], o1[8] };
        out4[3 * i1 + 0] = oa1;
        out4[3 * i1 + 1] = ob1;
        out4[3 * i1 + 2] = oc1;
    }
}

extern "C" void kernel_launch(void* const* d_in, const int* in_sizes, int n_in,
                              void* d_out, int out_size)
{
    const float4* st = (const float4*)d_in[0];
    const float4* u  = (const float4*)d_in[1];
    const float*  I  = (const float*)d_in[2];
    const float*  g  = (const float*)d_in[3];
    float4* out = (float4*)d_out;

    int B = in_sizes[0] / 12;
    int nthread = (B + 1) / 2;          // 2 rows per thread
    int threads = 128;
    int blocks = (nthread + threads - 1) / threads;
    drone_rk4_kernel<<<blocks, threads>>>(st, u, I, g, out, B);
}

// round 5
// speedup vs baseline: 1.6137x; 1.6137x over previous
#include <cuda_runtime.h>

// Exact-rounding helpers: immune to fmad contraction / fast-math.
__device__ __forceinline__ float fm(float a, float b) { return __fmul_rn(a, b); }
__device__ __forceinline__ float fa(float a, float b) { return __fadd_rn(a, b); }
__device__ __forceinline__ float fs(float a, float b) { return __fsub_rn(a, b); }

// Dynamics derivative, replicating the reference op graph (order + rounding),
// with divisions by per-thread-constant divisors replaced by correctly-rounded
// reciprocal multiplies (<=1ulp perturbation, verified against rel-err budget).
// s = [vx,vy,vz, roll,pitch,yaw, wx,wy,wz]
__device__ __forceinline__ void dyn9(
    const float* __restrict__ s,
    float u0, float tx, float ty, float tz,
    float I0, float I1, float I2,
    float iI0, float iI1, float iI2,
    float g0, float g1, float g2,
    float* __restrict__ d)
{
    float vx = s[0], vy = s[1], vz = s[2];
    float wx = s[6], wy = s[7], wz = s[8];

    float sr, cr, sp, cp, sy, cy;
    sincosf(s[3], &sr, &cr);
    sincosf(s[4], &sp, &cp);
    sincosf(s[5], &sy, &cy);

    // R[:, :, 2]  (thrust column), left-assoc as in reference
    float r2x = fa(fm(fm(cy, sp), cr), fm(sy, sr));   // c_y*s_p*c_r + s_y*s_r
    float r2y = fs(fm(fm(sy, sp), cr), fm(cy, sr));   // s_y*s_p*c_r - c_y*s_r
    float r2z = fm(cp, cr);                           // c_p*c_r

    // v_norm = max(sqrt(vx^2+vy^2+vz^2), 1e-8)
    float n2 = fa(fa(fm(vx, vx), fm(vy, vy)), fm(vz, vz));
    float vn = fmaxf(__fsqrt_rn(n2), 1e-8f);

    // drag = (-K_DRAG * v_norm) * vel ; acc = thrust + drag + g
    float nk = fm(-0.05f, vn);
    d[0] = fa(fa(fm(r2x, u0), fm(nk, vx)), g0);
    d[1] = fa(fa(fm(r2y, u0), fm(nk, vy)), g1);
    d[2] = fa(fa(fm(r2z, u0), fm(nk, vz)), g2);

    // omega_cross = cross(omega, omega*I);  omega_dot = (tau - cross) * (1/I)
    float bx = fm(wx, I0), by = fm(wy, I1), bz = fm(wz, I2);
    float cxv = fs(fm(wy, bz), fm(wz, by));
    float cyv = fs(fm(wz, bx), fm(wx, bz));
    float czv = fs(fm(wx, by), fm(wy, bx));
    d[6] = fm(fs(tx, cxv), iI0);
    d[7] = fm(fs(ty, cyv), iI1);
    d[8] = fm(fs(tz, czv), iI2);

    // attitude kinematics: one correctly-rounded reciprocal, three multiplies
    float cpit = (fabsf(cp) < 1e-6f) ? 1e-6f : cp;
    float icp  = __frcp_rn(cpit);
    float tp   = fm(sp, icp);
    d[3] = fa(fa(wx, fm(fm(sr, tp), wy)), fm(fm(cr, tp), wz));
    d[4] = fs(fm(cr, wy), fm(sr, wz));
    d[5] = fa(fm(fm(sr, icp), wy), fm(fm(cr, icp), wz));
}

__global__ void __launch_bounds__(256, 4)
drone_rk4_kernel(const float4* __restrict__ st4,
                 const float4* __restrict__ u4,
                 const float*  __restrict__ Ip,
                 const float*  __restrict__ gp,
                 float4* __restrict__ out4,
                 int B)
{
    int i = blockIdx.x * blockDim.x + threadIdx.x;
    if (i >= B) return;

    float4 a = st4[3 * i + 0];   // p0 p1 p2 v0
    float4 b = st4[3 * i + 1];   // v1 v2 r  p
    float4 c = st4[3 * i + 2];   // y  w0 w1 w2
    float4 uu = u4[i];           // u0 tau0 tau1 tau2

    float I0 = __ldg(Ip + 0), I1 = __ldg(Ip + 1), I2 = __ldg(Ip + 2);
    float g0 = __ldg(gp + 0), g1 = __ldg(gp + 1), g2 = __ldg(gp + 2);
    float iI0 = __frcp_rn(I0), iI1 = __frcp_rn(I1), iI2 = __frcp_rn(I2);

    float y[9] = { a.w, b.x, b.y,   // vel
                   b.z, b.w, c.x,   // att
                   c.y, c.z, c.w }; // omega

    const float H2 = 0.005f;                  // 0.5*DT
    const float H1 = 0.01f;                   // DT
    const float W6 = (float)(0.01 / 6.0);     // DT/6 rounded to f32

    float k[9], t[9], acc[9];
    float apx, apy, apz;   // position accumulator

    // ---- k1 ----
    dyn9(y, uu.x, uu.y, uu.z, uu.w, I0, I1, I2, iI0, iI1, iI2, g0, g1, g2, k);
    #pragma unroll
    for (int j = 0; j < 9; j++) { acc[j] = k[j]; t[j] = fa(y[j], fm(H2, k[j])); }
    apx = fa(y[0], fm(2.0f, t[0]));
    apy = fa(y[1], fm(2.0f, t[1]));
    apz = fa(y[2], fm(2.0f, t[2]));

    // ---- k2 ----
    dyn9(t, uu.x, uu.y, uu.z, uu.w, I0, I1, I2, iI0, iI1, iI2, g0, g1, g2, k);
    #pragma unroll
    for (int j = 0; j < 9; j++) { acc[j] = fa(acc[j], fm(2.0f, k[j])); t[j] = fa(y[j], fm(H2, k[j])); }
    apx = fa(apx, fm(2.0f, t[0]));
    apy = fa(apy, fm(2.0f, t[1]));
    apz = fa(apz, fm(2.0f, t[2]));

    // ---- k3 ----
    dyn9(t, uu.x, uu.y, uu.z, uu.w, I0, I1, I2, iI0, iI1, iI2, g0, g1, g2, k);
    #pragma unroll
    for (int j = 0; j < 9; j++) { acc[j] = fa(acc[j], fm(2.0f, k[j])); t[j] = fa(y[j], fm(H1, k[j])); }
    apx = fa(apx, t[0]);
    apy = fa(apy, t[1]);
    apz = fa(apz, t[2]);

    // ---- k4 ----
    dyn9(t, uu.x, uu.y, uu.z, uu.w, I0, I1, I2, iI0, iI1, iI2, g0, g1, g2, k);
    #pragma unroll
    for (int j = 0; j < 9; j++) acc[j] = fa(acc[j], k[j]);

    // out = state + W6 * acc
    float4 oa, ob, oc;
    oa.x = fa(a.x, fm(W6, apx));
    oa.y = fa(a.y, fm(W6, apy));
    oa.z = fa(a.z, fm(W6, apz));
    oa.w = fa(y[0], fm(W6, acc[0]));
    ob.x = fa(y[1], fm(W6, acc[1]));
    ob.y = fa(y[2], fm(W6, acc[2]));
    ob.z = fa(y[3], fm(W6, acc[3]));
    ob.w = fa(y[4], fm(W6, acc[4]));
    oc.x = fa(y[5], fm(W6, acc[5]));
    oc.y = fa(y[6], fm(W6, acc[6]));
    oc.z = fa(y[7], fm(W6, acc[7]));
    oc.w = fa(y[8], fm(W6, acc[8]));

    out4[3 * i + 0] = oa;
    out4[3 * i + 1] = ob;
    out4[3 * i + 2] = oc;
}

extern "C" void kernel_launch(void* const* d_in, const int* in_sizes, int n_in,
                              void* d_out, int out_size)
{
    const float4* st = (const float4*)d_in[0];
    const float4* u  = (const float4*)d_in[1];
    const float*  I  = (const float*)d_in[2];
    const float*  g  = (const float*)d_in[3];
    float4* out = (float4*)d_out;

    int B = in_sizes[0] / 12;
    int threads = 256;
    int blocks = (B + threads - 1) / threads;
    drone_rk4_kernel<<<blocks, threads>>>(st, u, I, g, out, B);
}

// round 6
// speedup vs baseline: 1.9326x; 1.1976x over previous
#include <cuda_runtime.h>

// Pitch-critical ops keep explicit .rn intrinsics; everything else is free to
// fuse (fmaf) — perturbations there are not chaotically amplified.
__device__ __forceinline__ float fm(float a, float b) { return __fmul_rn(a, b); }

// s = [vx,vy,vz, roll,pitch,yaw, wx,wy,wz]
// d = [ax,ay,az, roll_dot,pitch_dot,yaw_dot, wdx,wdy,wdz]
__device__ __forceinline__ void dyn9(
    const float* __restrict__ s,
    float u0, float tx, float ty, float tz,
    float I0, float I1, float I2,
    float iI0, float iI1, float iI2,
    float g0, float g1, float g2,
    float* __restrict__ d)
{
    float vx = s[0], vy = s[1], vz = s[2];
    float wx = s[6], wy = s[7], wz = s[8];

    // roll & pitch: accurate libdevice sincos (bit-exact vs reference's sin/cos).
    // yaw: MUFU fast path — feeds only the thrust column (velocity path, gain ~dt).
    float sr, cr, sp, cp, sy, cy;
    sincosf(s[3], &sr, &cr);
    sincosf(s[4], &sp, &cp);
    __sincosf(s[5], &sy, &cy);

    // R[:, :, 2] thrust column (velocity path — fusion safe)
    float spcr = sp * cr;
    float r2x = fmaf(cy, spcr, sy * sr);
    float r2y = fmaf(sy, spcr, -(cy * sr));
    float r2z = cp * cr;

    // v_norm = max(sqrt(|v|^2), 1e-8)
    float n2 = fmaf(vx, vx, fmaf(vy, vy, vz * vz));
    float vn = fmaxf(__fsqrt_rn(n2), 1e-8f);
    float nk = -0.05f * vn;

    d[0] = fmaf(r2x, u0, fmaf(nk, vx, g0));
    d[1] = fmaf(r2y, u0, fmaf(nk, vy, g1));
    d[2] = fmaf(r2z, u0, fmaf(nk, vz, g2));

    // omega_dot = (tau - omega x (omega*I)) * (1/I)
    float bx = wx * I0, by = wy * I1, bz = wz * I2;
    float cxv = fmaf(wy, bz, -(wz * by));
    float cyv = fmaf(wz, bx, -(wx * bz));
    float czv = fmaf(wx, by, -(wy * bx));
    d[6] = (tx - cxv) * iI0;
    d[7] = (ty - cyv) * iI1;
    d[8] = (tz - czv) * iI2;

    // attitude kinematics — cp/icp/tp chain kept in exact .rn form (THE amplifier)
    float cpit = (fabsf(cp) < 1e-6f) ? 1e-6f : cp;
    float icp  = __frcp_rn(cpit);
    float tp   = fm(sp, icp);
    float srtp = sr * tp,  crtp = cr * tp;
    float srip = sr * icp, crip = cr * icp;
    d[3] = fmaf(crtp, wz, fmaf(srtp, wy, wx));
    d[4] = fmaf(cr, wy, -(sr * wz));
    d[5] = fmaf(srip, wy, crip * wz);
}

__global__ void __launch_bounds__(256, 4)
drone_rk4_kernel(const float4* __restrict__ st4,
                 const float4* __restrict__ u4,
                 const float*  __restrict__ Ip,
                 const float*  __restrict__ gp,
                 float4* __restrict__ out4,
                 int B)
{
    int i = blockIdx.x * blockDim.x + threadIdx.x;
    if (i >= B) return;

    float4 a = st4[3 * i + 0];   // p0 p1 p2 v0
    float4 b = st4[3 * i + 1];   // v1 v2 r  p
    float4 c = st4[3 * i + 2];   // y  w0 w1 w2
    float4 uu = u4[i];           // u0 tau0 tau1 tau2

    float I0 = __ldg(Ip + 0), I1 = __ldg(Ip + 1), I2 = __ldg(Ip + 2);
    float g0 = __ldg(gp + 0), g1 = __ldg(gp + 1), g2 = __ldg(gp + 2);
    float iI0 = __frcp_rn(I0), iI1 = __frcp_rn(I1), iI2 = __frcp_rn(I2);

    float y[9] = { a.w, b.x, b.y,   // vel
                   b.z, b.w, c.x,   // att
                   c.y, c.z, c.w }; // omega

    const float H2 = 0.005f;                  // 0.5*DT
    const float H1 = 0.01f;                   // DT
    const float W6 = (float)(0.01 / 6.0);     // DT/6

    float k[9], t[9], acc[9];
    float apx, apy, apz;   // position (velocity-Simpson) accumulator

    // ---- k1 ----
    dyn9(y, uu.x, uu.y, uu.z, uu.w, I0, I1, I2, iI0, iI1, iI2, g0, g1, g2, k);
    #pragma unroll
    for (int j = 0; j < 9; j++) { acc[j] = k[j]; t[j] = fmaf(H2, k[j], y[j]); }
    apx = fmaf(2.0f, t[0], y[0]);
    apy = fmaf(2.0f, t[1], y[1]);
    apz = fmaf(2.0f, t[2], y[2]);

    // ---- k2 ----
    dyn9(t, uu.x, uu.y, uu.z, uu.w, I0, I1, I2, iI0, iI1, iI2, g0, g1, g2, k);
    #pragma unroll
    for (int j = 0; j < 9; j++) { acc[j] = fmaf(2.0f, k[j], acc[j]); t[j] = fmaf(H2, k[j], y[j]); }
    apx = fmaf(2.0f, t[0], apx);
    apy = fmaf(2.0f, t[1], apy);
    apz = fmaf(2.0f, t[2], apz);

    // ---- k3 ----
    dyn9(t, uu.x, uu.y, uu.z, uu.w, I0, I1, I2, iI0, iI1, iI2, g0, g1, g2, k);
    #pragma unroll
    for (int j = 0; j < 9; j++) { acc[j] = fmaf(2.0f, k[j], acc[j]); t[j] = fmaf(H1, k[j], y[j]); }
    apx += t[0];
    apy += t[1];
    apz += t[2];

    // ---- k4 ----
    dyn9(t, uu.x, uu.y, uu.z, uu.w, I0, I1, I2, iI0, iI1, iI2, g0, g1, g2, k);
    #pragma unroll
    for (int j = 0; j < 9; j++) acc[j] += k[j];

    // out = state + W6 * acc
    float4 oa, ob, oc;
    oa.x = fmaf(W6, apx, a.x);
    oa.y = fmaf(W6, apy, a.y);
    oa.z = fmaf(W6, apz, a.z);
    oa.w = fmaf(W6, acc[0], y[0]);
    ob.x = fmaf(W6, acc[1], y[1]);
    ob.y = fmaf(W6, acc[2], y[2]);
    ob.z = fmaf(W6, acc[3], y[3]);
    ob.w = fmaf(W6, acc[4], y[4]);
    oc.x = fmaf(W6, acc[5], y[5]);
    oc.y = fmaf(W6, acc[6], y[6]);
    oc.z = fmaf(W6, acc[7], y[7]);
    oc.w = fmaf(W6, acc[8], y[8]);

    out4[3 * i + 0] = oa;
    out4[3 * i + 1] = ob;
    out4[3 * i + 2] = oc;
}

extern "C" void kernel_launch(void* const* d_in, const int* in_sizes, int n_in,
                              void* d_out, int out_size)
{
    const float4* st = (const float4*)d_in[0];
    const float4* u  = (const float4*)d_in[1];
    const float*  I  = (const float*)d_in[2];
    const float*  g  = (const float*)d_in[3];
    float4* out = (float4*)d_out;

    int B = in_sizes[0] / 12;
    int threads = 256;
    int blocks = (B + threads - 1) / threads;
    drone_rk4_kernel<<<blocks, threads>>>(st, u, I, g, out, B);
}

// round 7
// speedup vs baseline: 2.0104x; 1.0403x over previous
#include <cuda_runtime.h>

// Pitch-critical ops keep explicit .rn intrinsics (the chaotic amplifier is the
// relative accuracy of cos(pitch) near its zeros). Everything else may fuse.
__device__ __forceinline__ float fm(float a, float b) { return __fmul_rn(a, b); }

// s = [vx,vy,vz, roll,pitch,yaw, wx,wy,wz]
// d = [ax,ay,az, roll_dot,pitch_dot,yaw_dot, wdx,wdy,wdz]
__device__ __forceinline__ void dyn9(
    const float* __restrict__ s,
    float u0, float tx, float ty, float tz,
    float I0, float I1, float I2,
    float iI0, float iI1, float iI2,
    float g0, float g1, float g2,
    float* __restrict__ d)
{
    float vx = s[0], vy = s[1], vz = s[2];
    float wx = s[6], wy = s[7], wz = s[8];

    // pitch: accurate libdevice sincos (relative accuracy of cp is load-bearing).
    // roll & yaw: MUFU fast path — only absolute (~1e-6) accuracy needed there.
    float sr, cr, sp, cp, sy, cy;
    __sincosf(s[3], &sr, &cr);
    sincosf(s[4], &sp, &cp);
    __sincosf(s[5], &sy, &cy);

    // R[:, :, 2] thrust column (velocity path — fusion safe)
    float spcr = sp * cr;
    float r2x = fmaf(cy, spcr, sy * sr);
    float r2y = fmaf(sy, spcr, -(cy * sr));
    float r2z = cp * cr;

    // v_norm = max(sqrt(|v|^2), 1e-8)
    float n2 = fmaf(vx, vx, fmaf(vy, vy, vz * vz));
    float vn = fmaxf(__fsqrt_rn(n2), 1e-8f);
    float nk = -0.05f * vn;

    d[0] = fmaf(r2x, u0, fmaf(nk, vx, g0));
    d[1] = fmaf(r2y, u0, fmaf(nk, vy, g1));
    d[2] = fmaf(r2z, u0, fmaf(nk, vz, g2));

    // omega_dot = (tau - omega x (omega*I)) * (1/I)
    float bx = wx * I0, by = wy * I1, bz = wz * I2;
    float cxv = fmaf(wy, bz, -(wz * by));
    float cyv = fmaf(wz, bx, -(wx * bz));
    float czv = fmaf(wx, by, -(wy * bx));
    d[6] = (tx - cxv) * iI0;
    d[7] = (ty - cyv) * iI1;
    d[8] = (tz - czv) * iI2;

    // attitude kinematics — cp/icp/tp chain kept in exact .rn form
    float cpit = (fabsf(cp) < 1e-6f) ? 1e-6f : cp;
    float icp  = __frcp_rn(cpit);
    float tp   = fm(sp, icp);
    float srtp = sr * tp,  crtp = cr * tp;
    float srip = sr * icp, crip = cr * icp;
    d[3] = fmaf(crtp, wz, fmaf(srtp, wy, wx));
    d[4] = fmaf(cr, wy, -(sr * wz));
    d[5] = fmaf(srip, wy, crip * wz);
}

__global__ void __launch_bounds__(256, 4)
drone_rk4_kernel(const float4* __restrict__ st4,
                 const float4* __restrict__ u4,
                 const float*  __restrict__ Ip,
                 const float*  __restrict__ gp,
                 float4* __restrict__ out4,
                 int B)
{
    int i = blockIdx.x * blockDim.x + threadIdx.x;
    if (i >= B) return;

    // Streaming loads: data is touched exactly once — evict-first in L2.
    float4 a = __ldcs(&st4[3 * i + 0]);   // p0 p1 p2 v0
    float4 b = __ldcs(&st4[3 * i + 1]);   // v1 v2 r  p
    float4 c = __ldcs(&st4[3 * i + 2]);   // y  w0 w1 w2
    float4 uu = __ldcs(&u4[i]);           // u0 tau0 tau1 tau2

    float I0 = __ldg(Ip + 0), I1 = __ldg(Ip + 1), I2 = __ldg(Ip + 2);
    float g0 = __ldg(gp + 0), g1 = __ldg(gp + 1), g2 = __ldg(gp + 2);
    float iI0 = __frcp_rn(I0), iI1 = __frcp_rn(I1), iI2 = __frcp_rn(I2);

    float y[9] = { a.w, b.x, b.y,   // vel
                   b.z, b.w, c.x,   // att
                   c.y, c.z, c.w }; // omega

    const float H2 = 0.005f;                  // 0.5*DT
    const float H1 = 0.01f;                   // DT
    const float W6 = (float)(0.01 / 6.0);     // DT/6

    float k[9], t[9], acc[9];
    float apx, apy, apz;   // position (velocity-Simpson) accumulator

    // ---- k1 ----
    dyn9(y, uu.x, uu.y, uu.z, uu.w, I0, I1, I2, iI0, iI1, iI2, g0, g1, g2, k);
    #pragma unroll
    for (int j = 0; j < 9; j++) { acc[j] = k[j]; t[j] = fmaf(H2, k[j], y[j]); }
    apx = fmaf(2.0f, t[0], y[0]);
    apy = fmaf(2.0f, t[1], y[1]);
    apz = fmaf(2.0f, t[2], y[2]);

    // ---- k2 ----
    dyn9(t, uu.x, uu.y, uu.z, uu.w, I0, I1, I2, iI0, iI1, iI2, g0, g1, g2, k);
    #pragma unroll
    for (int j = 0; j < 9; j++) { acc[j] = fmaf(2.0f, k[j], acc[j]); t[j] = fmaf(H2, k[j], y[j]); }
    apx = fmaf(2.0f, t[0], apx);
    apy = fmaf(2.0f, t[1], apy);
    apz = fmaf(2.0f, t[2], apz);

    // ---- k3 ----
    dyn9(t, uu.x, uu.y, uu.z, uu.w, I0, I1, I2, iI0, iI1, iI2, g0, g1, g2, k);
    #pragma unroll
    for (int j = 0; j < 9; j++) { acc[j] = fmaf(2.0f, k[j], acc[j]); t[j] = fmaf(H1, k[j], y[j]); }
    apx += t[0];
    apy += t[1];
    apz += t[2];

    // ---- k4 ----
    dyn9(t, uu.x, uu.y, uu.z, uu.w, I0, I1, I2, iI0, iI1, iI2, g0, g1, g2, k);
    #pragma unroll
    for (int j = 0; j < 9; j++) acc[j] += k[j];

    // out = state + W6 * acc  — streaming stores (never re-read)
    float4 oa, ob, oc;
    oa.x = fmaf(W6, apx, a.x);
    oa.y = fmaf(W6, apy, a.y);
    oa.z = fmaf(W6, apz, a.z);
    oa.w = fmaf(W6, acc[0], y[0]);
    ob.x = fmaf(W6, acc[1], y[1]);
    ob.y = fmaf(W6, acc[2], y[2]);
    ob.z = fmaf(W6, acc[3], y[3]);
    ob.w = fmaf(W6, acc[4], y[4]);
    oc.x = fmaf(W6, acc[5], y[5]);
    oc.y = fmaf(W6, acc[6], y[6]);
    oc.z = fmaf(W6, acc[7], y[7]);
    oc.w = fmaf(W6, acc[8], y[8]);

    __stcs(&out4[3 * i + 0], oa);
    __stcs(&out4[3 * i + 1], ob);
    __stcs(&out4[3 * i + 2], oc);
}

extern "C" void kernel_launch(void* const* d_in, const int* in_sizes, int n_in,
                              void* d_out, int out_size)
{
    const float4* st = (const float4*)d_in[0];
    const float4* u  = (const float4*)d_in[1];
    const float*  I  = (const float*)d_in[2];
    const float*  g  = (const float*)d_in[3];
    float4* out = (float4*)d_out;

    int B = in_sizes[0] / 12;
    int threads = 256;
    int blocks = (B + threads - 1) / threads;
    drone_rk4_kernel<<<blocks, threads>>>(st, u, I, g, out, B);
}

// round 8
// speedup vs baseline: 2.1039x; 1.0465x over previous
#include <cuda_runtime.h>

// Approx-MUFU helpers: RELATIVE error ~2e-7 — measured (R5/R6) to pass through
// the dynamics at ~unit gain, far under the 1e-3 gate. The only fatal error
// class is an ABSOLUTE-error floor on cos(pitch) (kills its relative accuracy
// near zeros), so pitch trig stays libdevice-accurate.
__device__ __forceinline__ float frcp_fast(float x) {
    float r; asm("rcp.approx.f32 %0, %1;" : "=f"(r) : "f"(x)); return r;
}
__device__ __forceinline__ float fsqrt_fast(float x) {
    float r; asm("sqrt.approx.f32 %0, %1;" : "=f"(r) : "f"(x)); return r;
}

// s = [vx,vy,vz, roll,pitch,yaw, wx,wy,wz]
// d = [ax,ay,az, roll_dot,pitch_dot,yaw_dot, wdx,wdy,wdz]
__device__ __forceinline__ void dyn9(
    const float* __restrict__ s,
    float u0, float tx, float ty, float tz,
    float I0, float I1, float I2,
    float iI0, float iI1, float iI2,
    float g0, float g1, float g2,
    float* __restrict__ d)
{
    float vx = s[0], vy = s[1], vz = s[2];
    float wx = s[6], wy = s[7], wz = s[8];

    // pitch: accurate libdevice sincos (cp relative accuracy is load-bearing).
    // roll & yaw: MUFU fast path (absolute ~1e-6 suffices there).
    float sr, cr, sp, cp, sy, cy;
    __sincosf(s[3], &sr, &cr);
    sincosf(s[4], &sp, &cp);
    __sincosf(s[5], &sy, &cy);

    // R[:, :, 2] thrust column
    float spcr = sp * cr;
    float r2x = fmaf(cy, spcr, sy * sr);
    float r2y = fmaf(sy, spcr, -(cy * sr));
    float r2z = cp * cr;

    // drag coefficient
    float n2 = fmaf(vx, vx, fmaf(vy, vy, vz * vz));
    float vn = fmaxf(fsqrt_fast(n2), 1e-8f);
    float nk = -0.05f * vn;

    d[0] = fmaf(r2x, u0, fmaf(nk, vx, g0));
    d[1] = fmaf(r2y, u0, fmaf(nk, vy, g1));
    d[2] = fmaf(r2z, u0, fmaf(nk, vz, g2));

    // omega_dot = (tau - omega x (omega*I)) * (1/I)
    float bx = wx * I0, by = wy * I1, bz = wz * I2;
    float cxv = fmaf(wy, bz, -(wz * by));
    float cyv = fmaf(wz, bx, -(wx * bz));
    float czv = fmaf(wx, by, -(wy * bx));
    d[6] = (tx - cxv) * iI0;
    d[7] = (ty - cyv) * iI1;
    d[8] = (tz - czv) * iI2;

    // attitude kinematics: q = sr*wy + cr*wz shared between roll_dot and yaw_dot
    float cpit = (fabsf(cp) < 1e-6f) ? 1e-6f : cp;
    float icp  = frcp_fast(cpit);          // relative-error perturbation only
    float tp   = sp * icp;
    float q    = fmaf(sr, wy, cr * wz);
    d[3] = fmaf(tp, q, wx);
    d[4] = fmaf(cr, wy, -(sr * wz));
    d[5] = q * icp;
}

__global__ void __launch_bounds__(256, 4)
drone_rk4_kernel(const float4* __restrict__ st4,
                 const float4* __restrict__ u4,
                 const float*  __restrict__ Ip,
                 const float*  __restrict__ gp,
                 float4* __restrict__ out4,
                 int B)
{
    int i = blockIdx.x * blockDim.x + threadIdx.x;
    if (i >= B) return;

    // Streaming loads: touched once — evict-first.
    float4 a = __ldcs(&st4[3 * i + 0]);   // p0 p1 p2 v0
    float4 b = __ldcs(&st4[3 * i + 1]);   // v1 v2 r  p
    float4 c = __ldcs(&st4[3 * i + 2]);   // y  w0 w1 w2
    float4 uu = __ldcs(&u4[i]);           // u0 tau0 tau1 tau2

    float I0 = __ldg(Ip + 0), I1 = __ldg(Ip + 1), I2 = __ldg(Ip + 2);
    float g0 = __ldg(gp + 0), g1 = __ldg(gp + 1), g2 = __ldg(gp + 2);
    float iI0 = __frcp_rn(I0), iI1 = __frcp_rn(I1), iI2 = __frcp_rn(I2);

    float y[9] = { a.w, b.x, b.y,   // vel
                   b.z, b.w, c.x,   // att
                   c.y, c.z, c.w }; // omega

    const float H2 = 0.005f;                  // 0.5*DT
    const float H1 = 0.01f;                   // DT
    const float W6 = (float)(0.01 / 6.0);     // DT/6

    float k[9], t[9], acc[9];
    float apx, apy, apz;

    // ---- k1 ----
    dyn9(y, uu.x, uu.y, uu.z, uu.w, I0, I1, I2, iI0, iI1, iI2, g0, g1, g2, k);
    #pragma unroll
    for (int j = 0; j < 9; j++) { acc[j] = k[j]; t[j] = fmaf(H2, k[j], y[j]); }
    apx = fmaf(2.0f, t[0], y[0]);
    apy = fmaf(2.0f, t[1], y[1]);
    apz = fmaf(2.0f, t[2], y[2]);

    // ---- k2 ----
    dyn9(t, uu.x, uu.y, uu.z, uu.w, I0, I1, I2, iI0, iI1, iI2, g0, g1, g2, k);
    #pragma unroll
    for (int j = 0; j < 9; j++) { acc[j] = fmaf(2.0f, k[j], acc[j]); t[j] = fmaf(H2, k[j], y[j]); }
    apx = fmaf(2.0f, t[0], apx);
    apy = fmaf(2.0f, t[1], apy);
    apz = fmaf(2.0f, t[2], apz);

    // ---- k3 ----
    dyn9(t, uu.x, uu.y, uu.z, uu.w, I0, I1, I2, iI0, iI1, iI2, g0, g1, g2, k);
    #pragma unroll
    for (int j = 0; j < 9; j++) { acc[j] = fmaf(2.0f, k[j], acc[j]); t[j] = fmaf(H1, k[j], y[j]); }
    apx += t[0];
    apy += t[1];
    apz += t[2];

    // ---- k4 ----
    dyn9(t, uu.x, uu.y, uu.z, uu.w, I0, I1, I2, iI0, iI1, iI2, g0, g1, g2, k);
    #pragma unroll
    for (int j = 0; j < 9; j++) acc[j] += k[j];

    // out = state + W6 * acc — streaming stores
    float4 oa, ob, oc;
    oa.x = fmaf(W6, apx, a.x);
    oa.y = fmaf(W6, apy, a.y);
    oa.z = fmaf(W6, apz, a.z);
    oa.w = fmaf(W6, acc[0], y[0]);
    ob.x = fmaf(W6, acc[1], y[1]);
    ob.y = fmaf(W6, acc[2], y[2]);
    ob.z = fmaf(W6, acc[3], y[3]);
    ob.w = fmaf(W6, acc[4], y[4]);
    oc.x = fmaf(W6, acc[5], y[5]);
    oc.y = fmaf(W6, acc[6], y[6]);
    oc.z = fmaf(W6, acc[7], y[7]);
    oc.w = fmaf(W6, acc[8], y[8]);

    __stcs(&out4[3 * i + 0], oa);
    __stcs(&out4[3 * i + 1], ob);
    __stcs(&out4[3 * i + 2], oc);
}

extern "C" void kernel_launch(void* const* d_in, const int* in_sizes, int n_in,
                              void* d_out, int out_size)
{
    const float4* st = (const float4*)d_in[0];
    const float4* u  = (const float4*)d_in[1];
    const float*  I  = (const float*)d_in[2];
    const float*  g  = (const float*)d_in[3];
    float4* out = (float4*)d_out;

    int B = in_sizes[0] / 12;
    int threads = 256;
    int blocks = (B + threads - 1) / threads;
    drone_rk4_kernel<<<blocks, threads>>>(st, u, I, g, out, B);
}

// round 9
// speedup vs baseline: 2.2116x; 1.0512x over previous
#include <cuda_runtime.h>

// Approx-MUFU helpers: RELATIVE error ~2e-7, measured harmless through the
// dynamics. Only the ABSOLUTE-error floor on cos(pitch) is fatal (kills its
// relative accuracy near zeros), so pitch trig stays libdevice-accurate.
__device__ __forceinline__ float frcp_fast(float x) {
    float r; asm("rcp.approx.f32 %0, %1;" : "=f"(r) : "f"(x)); return r;
}
__device__ __forceinline__ float fsqrt_fast(float x) {
    float r; asm("sqrt.approx.f32 %0, %1;" : "=f"(r) : "f"(x)); return r;
}

// s = [vx,vy,vz, roll,pitch,yaw, wx,wy,wz]
// d = [ax,ay,az, roll_dot,pitch_dot,yaw_dot, wdx,wdy,wdz]
// tau is pre-multiplied by 1/I (txI = tau_x * iI0, ...).
__device__ __forceinline__ void dyn9(
    const float* __restrict__ s,
    float u0, float txI, float tyI, float tzI,
    float I0, float I1, float I2,
    float iI0, float iI1, float iI2,
    float g0, float g1, float g2,
    float* __restrict__ d)
{
    float vx = s[0], vy = s[1], vz = s[2];
    float wx = s[6], wy = s[7], wz = s[8];

    // pitch: accurate libdevice sincos. roll & yaw: MUFU fast path.
    float sr, cr, sp, cp, sy, cy;
    __sincosf(s[3], &sr, &cr);
    sincosf(s[4], &sp, &cp);
    __sincosf(s[5], &sy, &cy);

    // R[:, :, 2] thrust column
    float spcr = sp * cr;
    float r2x = fmaf(cy, spcr, sy * sr);
    float r2y = fmaf(sy, spcr, -(cy * sr));
    float r2z = cp * cr;

    // drag coefficient
    float n2 = fmaf(vx, vx, fmaf(vy, vy, vz * vz));
    float vn = fmaxf(fsqrt_fast(n2), 1e-8f);
    float nk = -0.05f * vn;

    d[0] = fmaf(r2x, u0, fmaf(nk, vx, g0));
    d[1] = fmaf(r2y, u0, fmaf(nk, vy, g1));
    d[2] = fmaf(r2z, u0, fmaf(nk, vz, g2));

    // omega_dot = tau/I - (omega x (omega*I))/I   (tau/I pre-folded)
    float bx = wx * I0, by = wy * I1, bz = wz * I2;
    float cxv = fmaf(wy, bz, -(wz * by));
    float cyv = fmaf(wz, bx, -(wx * bz));
    float czv = fmaf(wx, by, -(wy * bx));
    d[6] = fmaf(-iI0, cxv, txI);
    d[7] = fmaf(-iI1, cyv, tyI);
    d[8] = fmaf(-iI2, czv, tzI);

    // attitude kinematics: q shared between roll_dot and yaw_dot
    float cpit = (fabsf(cp) < 1e-6f) ? 1e-6f : cp;
    float icp  = frcp_fast(cpit);
    float tp   = sp * icp;
    float q    = fmaf(sr, wy, cr * wz);
    d[3] = fmaf(tp, q, wx);
    d[4] = fmaf(cr, wy, -(sr * wz));
    d[5] = q * icp;
}

__global__ void __launch_bounds__(256, 5)
drone_rk4_kernel(const float4* __restrict__ st4,
                 const float4* __restrict__ u4,
                 const float*  __restrict__ Ip,
                 const float*  __restrict__ gp,
                 float4* __restrict__ out4,
                 int B)
{
    int i = blockIdx.x * blockDim.x + threadIdx.x;
    if (i >= B) return;

    // Streaming loads: touched once — evict-first.
    float4 a = __ldcs(&st4[3 * i + 0]);   // p0 p1 p2 v0
    float4 b = __ldcs(&st4[3 * i + 1]);   // v1 v2 r  p
    float4 c = __ldcs(&st4[3 * i + 2]);   // y  w0 w1 w2
    float4 uu = __ldcs(&u4[i]);           // u0 tau0 tau1 tau2

    float I0 = __ldg(Ip + 0), I1 = __ldg(Ip + 1), I2 = __ldg(Ip + 2);
    float g0 = __ldg(gp + 0), g1 = __ldg(gp + 1), g2 = __ldg(gp + 2);
    float iI0 = __frcp_rn(I0), iI1 = __frcp_rn(I1), iI2 = __frcp_rn(I2);
    float txI = uu.y * iI0, tyI = uu.z * iI1, tzI = uu.w * iI2;
    float u0  = uu.x;

    float y[9] = { a.w, b.x, b.y,   // vel
                   b.z, b.w, c.x,   // att
                   c.y, c.z, c.w }; // omega

    const float H2 = 0.005f;                  // 0.5*DT
    const float H1 = 0.01f;                   // DT
    const float W6 = (float)(0.01 / 6.0);     // DT/6

    float k[9], t[9], acc[9];
    float sx, sy_, sz;   // sum of k1..k3 velocity components (position path)

    // ---- k1 ----
    dyn9(y, u0, txI, tyI, tzI, I0, I1, I2, iI0, iI1, iI2, g0, g1, g2, k);
    #pragma unroll
    for (int j = 0; j < 9; j++) { acc[j] = k[j]; t[j] = fmaf(H2, k[j], y[j]); }
    sx = t[0]; sy_ = t[1]; sz = t[2];   // placeholder; recomputed below via sum form

    // position derivative sum: ap = 6*y_vel + DT*(a1+a2+a3) where a_i are the
    // stage ACCELERATIONS (k[0..2] of stages 1..3), since
    // 2*t2 + 2*t3 + t4 = 5*y + DT*(a1+a2+a3).  Track sacc = a1+a2+a3.
    float sax = k[0], say = k[1], saz = k[2];

    // ---- k2 ----
    dyn9(t, u0, txI, tyI, tzI, I0, I1, I2, iI0, iI1, iI2, g0, g1, g2, k);
    #pragma unroll
    for (int j = 0; j < 9; j++) { acc[j] = fmaf(2.0f, k[j], acc[j]); t[j] = fmaf(H2, k[j], y[j]); }
    sax += k[0]; say += k[1]; saz += k[2];

    // ---- k3 ----
    dyn9(t, u0, txI, tyI, tzI, I0, I1, I2, iI0, iI1, iI2, g0, g1, g2, k);
    #pragma unroll
    for (int j = 0; j < 9; j++) { acc[j] = fmaf(2.0f, k[j], acc[j]); t[j] = fmaf(H1, k[j], y[j]); }
    sax += k[0]; say += k[1]; saz += k[2];

    // ---- k4 ----
    dyn9(t, u0, txI, tyI, tzI, I0, I1, I2, iI0, iI1, iI2, g0, g1, g2, k);
    #pragma unroll
    for (int j = 0; j < 9; j++) acc[j] += k[j];

    // position: p + W6*(6*y_vel + DT*sacc) = p + DT*y_vel + (DT*DT/6)*sacc
    const float WP = (float)(0.01 * 0.01 / 6.0);
    float4 oa, ob, oc;
    oa.x = fmaf(WP, sax, fmaf(H1, y[0], a.x));
    oa.y = fmaf(WP, say, fmaf(H1, y[1], a.y));
    oa.z = fmaf(WP, saz, fmaf(H1, y[2], a.z));
    oa.w = fmaf(W6, acc[0], y[0]);
    ob.x = fmaf(W6, acc[1], y[1]);
    ob.y = fmaf(W6, acc[2], y[2]);
    ob.z = fmaf(W6, acc[3], y[3]);
    ob.w = fmaf(W6, acc[4], y[4]);
    oc.x = fmaf(W6, acc[5], y[5]);
    oc.y = fmaf(W6, acc[6], y[6]);
    oc.z = fmaf(W6, acc[7], y[7]);
    oc.w = fmaf(W6, acc[8], y[8]);
    (void)sx; (void)sy_; (void)sz;

    __stcs(&out4[3 * i + 0], oa);
    __stcs(&out4[3 * i + 1], ob);
    __stcs(&out4[3 * i + 2], oc);
}

extern "C" void kernel_launch(void* const* d_in, const int* in_sizes, int n_in,
                              void* d_out, int out_size)
{
    const float4* st = (const float4*)d_in[0];
    const float4* u  = (const float4*)d_in[1];
    const float*  I  = (const float*)d_in[2];
    const float*  g  = (const float*)d_in[3];
    float4* out = (float4*)d_out;

    int B = in_sizes[0] / 12;
    int threads = 256;
    int blocks = (B + threads - 1) / threads;
    drone_rk4_kernel<<<blocks, threads>>>(st, u, I, g, out, B);
}